// round 3
// baseline (speedup 1.0000x reference)
#include <cuda_runtime.h>

// Problem constants: N=100000, E=3200000, DIN=128, H=256, M=500, O=100
#define NN  100000
#define EE  3200000
#define DIN 128
#define HH  256
#define MM  500
#define MP  512   // padded M for GEMM3 A operand
#define OO  100

// ---- scratch (static device globals; referenced ONLY from device code) ----
__device__ int   g_deg[NN];
__device__ float g_dinv[NN];
__device__ __align__(16) float g_xagg[NN * DIN];   // 51.2 MB
__device__ __align__(16) float g_h   [NN * HH];    // 102.4 MB
__device__ __align__(16) float g_hagg[NN * HH];    // 102.4 MB
__device__ __align__(16) float g_p   [NN * MP];    // 204.8 MB (tanh(t*mr), zero-padded cols 500..511)

// ---------------- degree ----------------
__global__ void k_zero_deg() {
    int i = blockIdx.x * blockDim.x + threadIdx.x;
    if (i < NN) g_deg[i] = 0;
}

__global__ void k_count(const int* __restrict__ ei) {
    int e = blockIdx.x * blockDim.x + threadIdx.x;
    if (e < EE) {
        int d = ei[EE + e];            // dst row of edge_index (int32!)
        if ((unsigned)d < NN) atomicAdd(&g_deg[d], 1);
    }
}

__global__ void k_dinv() {
    int i = blockIdx.x * blockDim.x + threadIdx.x;
    if (i < NN) g_dinv[i] = rsqrtf((float)g_deg[i] + 2.0f);
}

// ---------------- self-loop init: AGG[i,:] = 2*dinv[i]^2 * X[i,:] ----------------
template<int LAYER>
__global__ void k_self(const float* __restrict__ Xin) {
    constexpr int C4 = (LAYER == 0 ? DIN : HH) / 4;
    const float* X = (LAYER == 0) ? Xin : (const float*)g_h;
    float* AGG = (LAYER == 0) ? g_xagg : g_hagg;
    int idx = blockIdx.x * blockDim.x + threadIdx.x;   // float4 index
    if (idx < NN * C4) {
        int node = idx / C4;
        float d = g_dinv[node];
        float sc = 2.0f * d * d;
        float4 v = ((const float4*)X)[idx];
        v.x *= sc; v.y *= sc; v.z *= sc; v.w *= sc;
        ((float4*)AGG)[idx] = v;
    }
}

// ---------------- edge scatter: AGG[dst,:] += coef * X[src,:]  (warp per edge) ----------------
template<int LAYER>
__global__ void k_scatter(const int* __restrict__ ei, const float* __restrict__ Xin) {
    constexpr int C = (LAYER == 0 ? DIN : HH);
    const float* X = (LAYER == 0) ? Xin : (const float*)g_h;
    float* AGG = (LAYER == 0) ? g_xagg : g_hagg;
    int w = (blockIdx.x * blockDim.x + threadIdx.x) >> 5;
    int lane = threadIdx.x & 31;
    if (w >= EE) return;
    int s = ei[w];
    int d = ei[EE + w];
    if ((unsigned)s >= NN || (unsigned)d >= NN) return;   // never trap
    float c = g_dinv[s] * g_dinv[d];
    const float4* xs = (const float4*)(X + (long)s * C);
    float* ad = AGG + (long)d * C;
#pragma unroll
    for (int r = 0; r < C / 128; r++) {
        float4 v = xs[lane + r * 32];
        int base = (lane + r * 32) * 4;
        atomicAdd(ad + base + 0, v.x * c);
        atomicAdd(ad + base + 1, v.y * c);
        atomicAdd(ad + base + 2, v.z * c);
        atomicAdd(ad + base + 3, v.w * c);
    }
}

// ---------------- tiled SGEMM: C = epi(A @ B + bias) ----------------
// BM=128, BN=64, BK=16, 256 threads, each 8x4 micro-tile.
// EPI 0: A=g_xagg K=128, C=g_h, ReLU.
// EPI 1: A=g_hagg K=256, C=out_mr (softplus) AND g_p = tanh(t*softplus) (ld MP, 0-pad).
// EPI 2: A=g_p K=512 (KB=500 guard on B), C=out_y, none.
template<int EPI>
__global__ void k_gemm(const float* __restrict__ B,
                       const float* __restrict__ bias, float* __restrict__ Cout,
                       const float* __restrict__ thrp) {
    constexpr int K     = (EPI == 0) ? DIN : (EPI == 1) ? HH : MP;
    constexpr int KB    = (EPI == 2) ? MM : K;      // valid K-rows of B
    constexpr int Nreal = (EPI == 0) ? HH : (EPI == 1) ? MM : OO;
    constexpr int ldc   = Nreal;
    const float* A = (EPI == 0) ? g_xagg : (EPI == 1) ? g_hagg : g_p;
    float* C = (EPI == 0) ? g_h : Cout;

    const int BM = 128, BN = 64, BK = 16;
    __shared__ float As[BK][BM];
    __shared__ float Bs[BK][BN + 4];
    int tid = threadIdx.x;
    int tx = tid & 15;   // col group (x4)
    int ty = tid >> 4;   // row group (x8)
    int rowBlk = blockIdx.y * BM;
    int colBlk = blockIdx.x * BN;

    float acc[8][4];
#pragma unroll
    for (int i = 0; i < 8; i++)
#pragma unroll
        for (int j = 0; j < 4; j++) acc[i][j] = 0.f;

    for (int kb = 0; kb < K; kb += BK) {
        // A tile: 128 rows x 16 k, as 512 float4 loads (2 per thread), stored transposed
#pragma unroll
        for (int i = 0; i < 2; i++) {
            int e = tid * 2 + i;          // 0..511
            int r = e >> 2;
            int c4 = e & 3;
            int gr = rowBlk + r;
            float4 v = make_float4(0.f, 0.f, 0.f, 0.f);
            if (gr < NN) v = *(const float4*)(A + (long)gr * K + kb + c4 * 4);
            As[c4 * 4 + 0][r] = v.x;
            As[c4 * 4 + 1][r] = v.y;
            As[c4 * 4 + 2][r] = v.z;
            As[c4 * 4 + 3][r] = v.w;
        }
        // B tile: 16 k x 64 n, scalar guarded loads (ldb == Nreal)
#pragma unroll
        for (int i = 0; i < 4; i++) {
            int e = tid + i * 256;
            int kk = e >> 6;
            int n = e & 63;
            int gk = kb + kk;
            int gn = colBlk + n;
            float v = 0.f;
            if (gk < KB && gn < Nreal) v = B[(long)gk * Nreal + gn];
            Bs[kk][n] = v;
        }
        __syncthreads();
#pragma unroll
        for (int k = 0; k < BK; k++) {
            float a[8], b[4];
#pragma unroll
            for (int i = 0; i < 8; i++) a[i] = As[k][ty * 8 + i];
#pragma unroll
            for (int j = 0; j < 4; j++) b[j] = Bs[k][tx * 4 + j];
#pragma unroll
            for (int i = 0; i < 8; i++)
#pragma unroll
                for (int j = 0; j < 4; j++) acc[i][j] += a[i] * b[j];
        }
        __syncthreads();
    }

    float t = 1.f;
    if (EPI == 1) {
        float th = *thrp;
        t = th > 0.f ? th + log1pf(expf(-th)) : log1pf(expf(th));
    }
#pragma unroll
    for (int i = 0; i < 8; i++) {
        int gr = rowBlk + ty * 8 + i;
        if (gr >= NN) continue;
#pragma unroll
        for (int j = 0; j < 4; j++) {
            int gn = colBlk + tx * 4 + j;
            float z = acc[i][j];
            if (EPI == 0) {
                if (gn < Nreal) C[(long)gr * ldc + gn] = fmaxf(z + bias[gn], 0.f);
            } else if (EPI == 1) {
                float p = 0.f;
                if (gn < Nreal) {
                    z += bias[gn];
                    float sp = z > 0.f ? z + log1pf(expf(-z)) : log1pf(expf(z));
                    C[(long)gr * ldc + gn] = sp;
                    p = tanhf(t * sp);
                }
                g_p[(long)gr * MP + gn] = p;   // zero-pad cols [Nreal, MP)
            } else {
                if (gn < Nreal) C[(long)gr * ldc + gn] = z + bias[gn];
            }
        }
    }
}

extern "C" void kernel_launch(void* const* d_in, const int* in_sizes, int n_in,
                              void* d_out, int out_size) {
    const float* x    = (const float*)d_in[0];
    const int*   ei   = (const int*)d_in[1];     // int32! (JAX x64 disabled downcasts int64)
    const float* W1   = (const float*)d_in[2];
    const float* b1   = (const float*)d_in[3];
    const float* W2   = (const float*)d_in[4];
    const float* b2   = (const float*)d_in[5];
    const float* Wout = (const float*)d_in[6];
    const float* bout = (const float*)d_in[7];
    const float* thr  = (const float*)d_in[8];
    float* out = (float*)d_out;
    float* out_mr = out;                  // [N, M]
    float* out_y  = out + (long)NN * MM;  // [N, O]

    // degrees + dinv
    k_zero_deg<<<(NN + 255) / 256, 256>>>();
    k_count<<<(EE + 255) / 256, 256>>>(ei);
    k_dinv<<<(NN + 255) / 256, 256>>>();

    // layer 1: xagg = self_coef*x + A_norm x ; h = relu(xagg@W1 + b1)
    k_self<0><<<(NN * (DIN / 4) + 255) / 256, 256>>>(x);
    k_scatter<0><<<(EE * 32 + 255) / 256, 256>>>(ei, x);
    {
        dim3 grid(HH / 64, (NN + 127) / 128);
        k_gemm<0><<<grid, 256>>>(W1, b1, nullptr, nullptr);
    }

    // layer 2: hagg = self_coef*h + A_norm h ; mr = softplus(hagg@W2 + b2); p = tanh(t*mr)
    k_self<1><<<(NN * (HH / 4) + 255) / 256, 256>>>(nullptr);
    k_scatter<1><<<(EE * 32 + 255) / 256, 256>>>(ei, nullptr);
    {
        dim3 grid(MP / 64, (NN + 127) / 128);   // cover 512 cols so g_p pad gets zeroed
        k_gemm<1><<<grid, 256>>>(W2, b2, out_mr, thr);
    }

    // head: y = p @ Wout + bout  (K padded to 512, B guarded at 500)
    {
        dim3 grid((OO + 63) / 64, (NN + 127) / 128);
        k_gemm<2><<<grid, 256>>>(Wout, bout, out_y, nullptr);
    }
}

// round 4
// speedup vs baseline: 2.0768x; 2.0768x over previous
#include <cuda_runtime.h>

// Problem constants: N=100000, E=3200000, DIN=128, H=256, M=500, O=100
#define NN  100000
#define EE  3200000
#define DIN 128
#define HH  256
#define MM  500
#define MP  512   // padded M for GEMM3 A operand
#define OO  100

#define SCAN_B 1024
#define NBLK ((NN + SCAN_B - 1) / SCAN_B)   // 98

// ---- scratch (static device globals; referenced ONLY from device code) ----
__device__ int   g_deg[NN];
__device__ int   g_off[NN];
__device__ int   g_cur[NN];
__device__ int   g_bsum[128];
__device__ int   g_src[EE];                        // CSR: src ids grouped by dst
__device__ float g_dinv[NN];
__device__ __align__(16) float g_xagg[NN * DIN];   // 51.2 MB
__device__ __align__(16) float g_h   [NN * HH];    // 102.4 MB
__device__ __align__(16) float g_hagg[NN * HH];    // 102.4 MB
__device__ __align__(16) float g_p   [NN * MP];    // 204.8 MB

// ---------------- degree / norm ----------------
__global__ void k_zero_deg() {
    int i = blockIdx.x * blockDim.x + threadIdx.x;
    if (i < NN) g_deg[i] = 0;
}

__global__ void k_count(const int* __restrict__ ei) {
    int e = blockIdx.x * blockDim.x + threadIdx.x;
    if (e < EE) {
        int d = ei[EE + e];
        if ((unsigned)d < NN) atomicAdd(&g_deg[d], 1);
    }
}

__global__ void k_dinv() {
    int i = blockIdx.x * blockDim.x + threadIdx.x;
    if (i < NN) g_dinv[i] = rsqrtf((float)g_deg[i] + 2.0f);
}

// ---------------- exclusive scan of degrees -> CSR offsets ----------------
__global__ void k_scan1() {
    __shared__ int sm[SCAN_B];
    int t = threadIdx.x, i = blockIdx.x * SCAN_B + t;
    int v = (i < NN) ? g_deg[i] : 0;
    sm[t] = v; __syncthreads();
    for (int s = 1; s < SCAN_B; s <<= 1) {
        int add = (t >= s) ? sm[t - s] : 0;
        __syncthreads();
        sm[t] += add; __syncthreads();
    }
    if (i < NN) g_off[i] = sm[t] - v;
    if (t == SCAN_B - 1) g_bsum[blockIdx.x] = sm[t];
}

__global__ void k_scan2() {
    __shared__ int sm[128];
    int t = threadIdx.x;
    int v = (t < NBLK) ? g_bsum[t] : 0;
    sm[t] = v; __syncthreads();
    for (int s = 1; s < 128; s <<= 1) {
        int add = (t >= s) ? sm[t - s] : 0;
        __syncthreads();
        sm[t] += add; __syncthreads();
    }
    if (t < NBLK) g_bsum[t] = sm[t] - v;   // exclusive
}

__global__ void k_scan3() {
    int i = blockIdx.x * blockDim.x + threadIdx.x;
    if (i < NN) {
        int o = g_off[i] + g_bsum[i / SCAN_B];
        g_off[i] = o;
        g_cur[i] = o;
    }
}

__global__ void k_fill(const int* __restrict__ ei) {
    int e = blockIdx.x * blockDim.x + threadIdx.x;
    if (e < EE) {
        int s = ei[e];
        int d = ei[EE + e];
        if ((unsigned)s < NN && (unsigned)d < NN) {
            int pos = atomicAdd(&g_cur[d], 1);
            g_src[pos] = s;
        }
    }
}

// ---------------- CSR gather: OUT[d, coff:coff+128] = self + sum_e coef*X[src] ----
// Warp per dst node, 128 channels per launch (lane*4 floats each).
template<int LAYER>
__global__ void k_gather(const float* __restrict__ Xin, int coff) {
    constexpr int C = (LAYER == 0) ? DIN : HH;
    const float* X = (LAYER == 0) ? Xin : (const float*)g_h;
    float* OUT = (LAYER == 0) ? g_xagg : g_hagg;
    int w = (blockIdx.x * blockDim.x + threadIdx.x) >> 5;
    int lane = threadIdx.x & 31;
    if (w >= NN) return;
    float dv = g_dinv[w];
    const float* Xc = X + coff + lane * 4;
    float4 acc;
    {
        float4 v = *(const float4*)(Xc + (long)w * C);
        float sc = 2.0f * dv * dv;
        acc.x = v.x * sc; acc.y = v.y * sc; acc.z = v.z * sc; acc.w = v.w * sc;
    }
    int off = g_off[w], dg = g_deg[w];
    int j = 0;
    for (; j + 2 <= dg; j += 2) {
        int s0 = g_src[off + j];
        int s1 = g_src[off + j + 1];
        float c0 = g_dinv[s0] * dv;
        float c1 = g_dinv[s1] * dv;
        float4 v0 = *(const float4*)(Xc + (long)s0 * C);
        float4 v1 = *(const float4*)(Xc + (long)s1 * C);
        acc.x += v0.x * c0; acc.y += v0.y * c0; acc.z += v0.z * c0; acc.w += v0.w * c0;
        acc.x += v1.x * c1; acc.y += v1.y * c1; acc.z += v1.z * c1; acc.w += v1.w * c1;
    }
    if (j < dg) {
        int s0 = g_src[off + j];
        float c0 = g_dinv[s0] * dv;
        float4 v0 = *(const float4*)(Xc + (long)s0 * C);
        acc.x += v0.x * c0; acc.y += v0.y * c0; acc.z += v0.z * c0; acc.w += v0.w * c0;
    }
    *(float4*)(OUT + coff + (long)w * C + lane * 4) = acc;
}

// ---------------- tiled SGEMM: C = epi(A @ B + bias) ----------------
// BM=128, BN=128, BK=8, 256 threads, 8x8 micro-tile.
// EPI 0: A=g_xagg K=128 -> C=g_h, ReLU.
// EPI 1: A=g_hagg K=256 -> out_mr (softplus) + g_p = tanh(t*softplus) (ld MP, 0-pad).
// EPI 2: A=g_p K=512 (KB=500 guard on B) -> out_y.
template<int EPI>
__global__ void k_gemm(const float* __restrict__ B,
                       const float* __restrict__ bias, float* __restrict__ Cout,
                       const float* __restrict__ thrp) {
    constexpr int K     = (EPI == 0) ? DIN : (EPI == 1) ? HH : MP;
    constexpr int KB    = (EPI == 2) ? MM : K;
    constexpr int Nreal = (EPI == 0) ? HH : (EPI == 1) ? MM : OO;
    constexpr int ldc   = Nreal;
    const float* A = (EPI == 0) ? g_xagg : (EPI == 1) ? g_hagg : g_p;
    float* C = (EPI == 0) ? g_h : Cout;

    const int BM = 128, BN = 128, BK = 8;
    __shared__ float As[BK][BM + 4];
    __shared__ float Bs[BK][BN + 4];
    int tid = threadIdx.x;
    int tx = tid & 15;    // 0..15, col group (x8)
    int ty = tid >> 4;    // 0..15, row group (x8)
    int rowBlk = blockIdx.y * BM;
    int colBlk = blockIdx.x * BN;

    float acc[8][8];
#pragma unroll
    for (int i = 0; i < 8; i++)
#pragma unroll
        for (int j = 0; j < 8; j++) acc[i][j] = 0.f;

    for (int kb = 0; kb < K; kb += BK) {
        // A tile: 128 rows x 8 k (row-major source), stored transposed As[k][m]
        {
            int row = tid >> 1, part = tid & 1;
            int gr = rowBlk + row;
            float4 v = make_float4(0.f, 0.f, 0.f, 0.f);
            if (gr < NN) v = *(const float4*)(A + (long)gr * K + kb + part * 4);
            As[part * 4 + 0][row] = v.x;
            As[part * 4 + 1][row] = v.y;
            As[part * 4 + 2][row] = v.z;
            As[part * 4 + 3][row] = v.w;
        }
        // B tile: 8 k x 128 n
        {
            int kk = tid >> 5, n4 = tid & 31;
            int gk = kb + kk, gn = colBlk + n4 * 4;
            float4 v = make_float4(0.f, 0.f, 0.f, 0.f);
            if (gk < KB) {
                if (gn + 3 < Nreal) {
                    v = *(const float4*)(B + (long)gk * Nreal + gn);
                } else {
                    if (gn + 0 < Nreal) v.x = B[(long)gk * Nreal + gn + 0];
                    if (gn + 1 < Nreal) v.y = B[(long)gk * Nreal + gn + 1];
                    if (gn + 2 < Nreal) v.z = B[(long)gk * Nreal + gn + 2];
                    if (gn + 3 < Nreal) v.w = B[(long)gk * Nreal + gn + 3];
                }
            }
            *(float4*)&Bs[kk][n4 * 4] = v;
        }
        __syncthreads();
#pragma unroll
        for (int k = 0; k < BK; k++) {
            float4 a0 = *(const float4*)&As[k][ty * 8];
            float4 a1 = *(const float4*)&As[k][ty * 8 + 4];
            float4 b0 = *(const float4*)&Bs[k][tx * 8];
            float4 b1 = *(const float4*)&Bs[k][tx * 8 + 4];
            float a[8] = {a0.x, a0.y, a0.z, a0.w, a1.x, a1.y, a1.z, a1.w};
            float b[8] = {b0.x, b0.y, b0.z, b0.w, b1.x, b1.y, b1.z, b1.w};
#pragma unroll
            for (int i = 0; i < 8; i++)
#pragma unroll
                for (int j = 0; j < 8; j++) acc[i][j] += a[i] * b[j];
        }
        __syncthreads();
    }

    float t = 1.f;
    if (EPI == 1) {
        float th = *thrp;
        t = th > 0.f ? th + log1pf(expf(-th)) : log1pf(expf(th));
    }
#pragma unroll
    for (int i = 0; i < 8; i++) {
        int gr = rowBlk + ty * 8 + i;
        if (gr >= NN) continue;
#pragma unroll
        for (int j = 0; j < 8; j++) {
            int gn = colBlk + tx * 8 + j;
            float z = acc[i][j];
            if (EPI == 0) {
                if (gn < Nreal) C[(long)gr * ldc + gn] = fmaxf(z + bias[gn], 0.f);
            } else if (EPI == 1) {
                float p = 0.f;
                if (gn < Nreal) {
                    z += bias[gn];
                    float sp = z > 0.f ? z + log1pf(expf(-z)) : log1pf(expf(z));
                    C[(long)gr * ldc + gn] = sp;
                    p = tanhf(t * sp);
                }
                g_p[(long)gr * MP + gn] = p;   // zero-pad cols [Nreal, MP)
            } else {
                if (gn < Nreal) C[(long)gr * ldc + gn] = z + bias[gn];
            }
        }
    }
}

extern "C" void kernel_launch(void* const* d_in, const int* in_sizes, int n_in,
                              void* d_out, int out_size) {
    const float* x    = (const float*)d_in[0];
    const int*   ei   = (const int*)d_in[1];     // int32 (JAX x64 disabled)
    const float* W1   = (const float*)d_in[2];
    const float* b1   = (const float*)d_in[3];
    const float* W2   = (const float*)d_in[4];
    const float* b2   = (const float*)d_in[5];
    const float* Wout = (const float*)d_in[6];
    const float* bout = (const float*)d_in[7];
    const float* thr  = (const float*)d_in[8];
    float* out = (float*)d_out;
    float* out_mr = out;                  // [N, M]
    float* out_y  = out + (long)NN * MM;  // [N, O]

    // graph preprocessing: degrees, dinv, CSR
    k_zero_deg<<<(NN + 255) / 256, 256>>>();
    k_count<<<(EE + 255) / 256, 256>>>(ei);
    k_dinv<<<(NN + 255) / 256, 256>>>();
    k_scan1<<<NBLK, SCAN_B>>>();
    k_scan2<<<1, 128>>>();
    k_scan3<<<(NN + 255) / 256, 256>>>();
    k_fill<<<(EE + 255) / 256, 256>>>(ei);

    int gatherBlocks = (NN * 32 + 255) / 256;   // warp per node

    // layer 1: xagg = self + A_norm x ; h = relu(xagg@W1 + b1)
    k_gather<0><<<gatherBlocks, 256>>>(x, 0);
    {
        dim3 grid(HH / 128, (NN + 127) / 128);
        k_gemm<0><<<grid, 256>>>(W1, b1, nullptr, nullptr);
    }

    // layer 2: hagg = self + A_norm h (two channel-half passes for L2 residency)
    k_gather<1><<<gatherBlocks, 256>>>(nullptr, 0);
    k_gather<1><<<gatherBlocks, 256>>>(nullptr, 128);
    {
        dim3 grid(MP / 128, (NN + 127) / 128);   // cover 512 cols so g_p pad is zeroed
        k_gemm<1><<<grid, 256>>>(W2, b2, out_mr, thr);
    }

    // head: y = p @ Wout + bout  (K padded to 512, B guarded at 500)
    {
        dim3 grid(1, (NN + 127) / 128);
        k_gemm<2><<<grid, 256>>>(Wout, bout, out_y, nullptr);
    }
}